// round 3
// baseline (speedup 1.0000x reference)
#include <cuda_runtime.h>
#include <cuda_bf16.h>
#include <math.h>

// Problem constants (fixed by the dataset)
#define MAX_VISITS   510
#define B_CAP        128
#define TOTAL_VISITS_CAP 38400
#define D_DIM        256
#define D_VEC        (D_DIM / 4)   // 64 float4 per row
#define MAX_DAYS_M1  364.0f
#define WARPS_PER_BLOCK 8

// Scratch (allocation-free rule: __device__ globals).
// Zero-initialized at module load. slot_map encodes v+1; 0 = pad row.
// Pad entries are never written (constant 0); visit entries are rewritten
// with identical values every call, so work/output are call-invariant.
__device__ int g_slot_map[B_CAP * MAX_VISITS];
__device__ int g_seg_start[TOTAL_VISITS_CAP];
__device__ int g_seg_end[TOTAL_VISITS_CAP];

// One thread handles 4 consecutive code_to_visit entries (int4) and detects
// segment boundaries; every visit has >=1 code so both bounds are always
// fully rewritten each call. Also scatters the visit->row map.
__global__ void vt_build_kernel(const int* __restrict__ code_to_visit,
                                const int* __restrict__ visit_person,
                                const int* __restrict__ visit_slot,
                                int total_codes, int total_visits) {
    int i = blockIdx.x * blockDim.x + threadIdx.x;
    int base = i * 4;
    if (base + 4 <= total_codes) {
        int4 c = *reinterpret_cast<const int4*>(code_to_visit + base);
        if (base == 0) g_seg_start[c.x] = 0;
        if (c.x != c.y) { g_seg_end[c.x] = base + 1; g_seg_start[c.y] = base + 1; }
        if (c.y != c.z) { g_seg_end[c.y] = base + 2; g_seg_start[c.z] = base + 2; }
        if (c.z != c.w) { g_seg_end[c.z] = base + 3; g_seg_start[c.w] = base + 3; }
        if (base + 4 == total_codes) {
            g_seg_end[c.w] = total_codes;
        } else {
            int nxt = code_to_visit[base + 4];
            if (c.w != nxt) { g_seg_end[c.w] = base + 4; g_seg_start[nxt] = base + 4; }
        }
    } else if (base < total_codes) {
        for (int k = base; k < total_codes; ++k) {
            int v = code_to_visit[k];
            if (k == 0 || code_to_visit[k - 1] != v) g_seg_start[v] = k;
            if (k == total_codes - 1 || code_to_visit[k + 1] != v) g_seg_end[v] = k + 1;
        }
    }
    if (i < total_visits) {
        g_slot_map[visit_person[i] * MAX_VISITS + visit_slot[i]] = i + 1;
    }
}

// ONE WARP PER OUTPUT ROW.
// Lane owns dims [4*lane, 4*lane+4)  (sin half, <128)
//       and dims [128+4*lane, ...)   (cos half) -- same timescales for both,
// so one timescale float4 + sincosf serves both halves.
// Indices for the row's codes are loaded once (lane j -> code j) and
// broadcast via __shfl_sync, removing 31/32 of the index LDG traffic.
__global__ __launch_bounds__(32 * WARPS_PER_BLOCK) void vt_main_kernel(
    const int* __restrict__ all_codes,
    const float* __restrict__ times,
    const float* __restrict__ concept_emb,
    const float* __restrict__ pad_embedding,
    const float* __restrict__ timescales,
    float* __restrict__ out,
    int n_rows) {
    int lane = threadIdx.x & 31;
    int row  = blockIdx.x * WARPS_PER_BLOCK + (threadIdx.x >> 5);
    if (row >= n_rows) return;

    float4* out4 = reinterpret_cast<float4*>(out);
    size_t obase = (size_t)row * D_VEC;

    int ve = g_slot_map[row];
    if (ve == 0) {
        const float4* pad4 = reinterpret_cast<const float4*>(pad_embedding);
        out4[obase + lane]      = __ldg(pad4 + lane);
        out4[obase + 32 + lane] = __ldg(pad4 + 32 + lane);
        return;
    }
    int v = ve - 1;

    int start = g_seg_start[v];
    int count = g_seg_end[v] - start;

    // Cooperative index load: lane j holds code j (count <= 15 in this dataset)
    int myc = 0;
    if (lane < count) myc = __ldg(all_codes + start + lane);

    const float4* emb4 = reinterpret_cast<const float4*>(concept_emb);
    float4 acc0 = make_float4(0.f, 0.f, 0.f, 0.f);   // dims 4*lane..
    float4 acc1 = make_float4(0.f, 0.f, 0.f, 0.f);   // dims 128+4*lane..

    int cap = (count < 32) ? count : 32;
    #pragma unroll 4
    for (int j = 0; j < cap; ++j) {
        int c = __shfl_sync(0xffffffffu, myc, j);
        const float4* rp = emb4 + (size_t)c * D_VEC + lane;
        float4 r0 = __ldg(rp);
        float4 r1 = __ldg(rp + 32);
        acc0.x += r0.x; acc0.y += r0.y; acc0.z += r0.z; acc0.w += r0.w;
        acc1.x += r1.x; acc1.y += r1.y; acc1.z += r1.z; acc1.w += r1.w;
    }
    // safety tail for count > 32 (never hit for this dataset)
    for (int j = 32; j < count; ++j) {
        int c = __ldg(all_codes + start + j);
        const float4* rp = emb4 + (size_t)c * D_VEC + lane;
        float4 r0 = __ldg(rp);
        float4 r1 = __ldg(rp + 32);
        acc0.x += r0.x; acc0.y += r0.y; acc0.z += r0.z; acc0.w += r0.w;
        acc1.x += r1.x; acc1.y += r1.y; acc1.z += r1.z; acc1.w += r1.w;
    }

    // Time embedding: out[d] += sin(t*ts[d]) for d<128, cos(t*ts[d-128]) else.
    float tm = __ldg(times + v);
    tm = fminf(fmaxf(tm, 0.0f), MAX_DAYS_M1);

    float4 ts = __ldg(reinterpret_cast<const float4*>(timescales) + lane);
    float s, c;
    __sincosf(tm * ts.x, &s, &c);
    // NOTE: __sincosf is fast-math; use precise sincosf for accuracy.
    (void)s; (void)c;
    {
        float s0, c0, s1, c1, s2, c2, s3, c3;
        sincosf(tm * ts.x, &s0, &c0);
        sincosf(tm * ts.y, &s1, &c1);
        sincosf(tm * ts.z, &s2, &c2);
        sincosf(tm * ts.w, &s3, &c3);
        acc0.x += s0; acc0.y += s1; acc0.z += s2; acc0.w += s3;
        acc1.x += c0; acc1.y += c1; acc1.z += c2; acc1.w += c3;
    }

    out4[obase + lane]      = acc0;
    out4[obase + 32 + lane] = acc1;
}

extern "C" void kernel_launch(void* const* d_in, const int* in_sizes, int n_in,
                              void* d_out, int out_size) {
    const int*   all_codes     = (const int*)d_in[0];
    const int*   code_to_visit = (const int*)d_in[1];
    const int*   visit_person  = (const int*)d_in[2];
    const int*   visit_slot    = (const int*)d_in[3];
    const float* times         = (const float*)d_in[4];
    const float* concept_emb   = (const float*)d_in[5];
    const float* pad_embedding = (const float*)d_in[6];
    const float* timescales    = (const float*)d_in[7];
    float* out = (float*)d_out;

    int total_codes  = in_sizes[0];
    int total_visits = in_sizes[2];
    int n_rows = out_size / D_DIM;   // B * MAX_VISITS

    int build_items = (total_codes + 3) / 4;
    if (build_items < total_visits) build_items = total_visits;
    vt_build_kernel<<<(build_items + 255) / 256, 256>>>(
        code_to_visit, visit_person, visit_slot, total_codes, total_visits);

    vt_main_kernel<<<(n_rows + WARPS_PER_BLOCK - 1) / WARPS_PER_BLOCK,
                     32 * WARPS_PER_BLOCK>>>(
        all_codes, times, concept_emb, pad_embedding, timescales, out, n_rows);
}